// round 16
// baseline (speedup 1.0000x reference)
#include <cuda_runtime.h>
#include <cuda_bf16.h>
#include <cstdint>
#include <cstddef>

#define BATCH 16384
#define CLS   2048
#define NN    4096   // 2*CLS

// ---------------- BF16 GEMM config ----------------
#define TM 128
#define TN 128
#define BKE 64                 // bf16 elems per stage row = 128 bytes
#define PITCHB 144             // bytes per smem row (128 data + 16 pad, conflict-free ldmatrix)
#define STAGES 3
#define NITER (BATCH / BKE)    // 256
#define A_STAGE (TM * PITCHB)  // 18432 bytes
#define STAGE_BYTES (2 * A_STAGE)            // 36864
#define SMEM_BYTES (STAGES * STAGE_BYTES)    // 110592
#define SMEM_TOTAL (SMEM_BYTES + 64)         // + mbarriers
#define NT1D (NN / TM)                        // 32
#define NTRI (NT1D * (NT1D + 1) / 2)          // 528 upper-triangular tiles

// ---------------- scratch (device globals) ----------------
__device__ __align__(16) __nv_bfloat16 g_X[(size_t)NN * BATCH];  // 128MB, K-major bf16
__device__ float g_colsum[NN];
__device__ float g_sumsq[NN];
__device__ float g_rowsum[NN];   // sum_{s!=r} exp(sim[r,s])
__device__ float g_pos[NN];      // sim[r, r^CLS]

// ---------------- helpers ----------------
__device__ __forceinline__ uint32_t smem_u32(const void* p) {
    uint32_t a;
    asm("{ .reg .u64 t; cvta.to.shared.u64 t, %1; cvt.u32.u64 %0, t; }" : "=r"(a) : "l"(p));
    return a;
}
__device__ __forceinline__ void cp_async16s(uint32_t dst, const void* src) {
    asm volatile("cp.async.cg.shared.global [%0], [%1], 16;\n" :: "r"(dst), "l"(src));
}
__device__ __forceinline__ void ldsm4(uint32_t& r0, uint32_t& r1, uint32_t& r2, uint32_t& r3,
                                      uint32_t addr) {
    asm volatile("ldmatrix.sync.aligned.m8n8.x4.shared.b16 {%0,%1,%2,%3}, [%4];\n"
                 : "=r"(r0), "=r"(r1), "=r"(r2), "=r"(r3) : "r"(addr));
}
// bf16 mma: m16n8k16, fp32 accum
__device__ __forceinline__ void mma_bf16(float* c, const uint32_t* a, uint32_t b0, uint32_t b1) {
    asm volatile(
        "mma.sync.aligned.m16n8k16.row.col.f32.bf16.bf16.f32 "
        "{%0,%1,%2,%3}, {%4,%5,%6,%7}, {%8,%9}, {%0,%1,%2,%3};\n"
        : "+f"(c[0]), "+f"(c[1]), "+f"(c[2]), "+f"(c[3])
        : "r"(a[0]), "r"(a[1]), "r"(a[2]), "r"(a[3]), "r"(b0), "r"(b1));
}

// ---------------- mbarrier primitives (base ISA) ----------------
#define MBARRIER_INIT(mb, cnt) \
    asm volatile("mbarrier.init.shared.b64 [%0], %1;" :: "r"((uint32_t)(mb)), "r"((uint32_t)(cnt)) : "memory")
#define MBARRIER_ARRIVE(mb) \
    asm volatile("mbarrier.arrive.shared.b64 _, [%0];" :: "r"((uint32_t)(mb)) : "memory")
#define CPASYNC_MBAR_ARRIVE(mb) \
    asm volatile("cp.async.mbarrier.arrive.noinc.shared.b64 [%0];" :: "r"((uint32_t)(mb)) : "memory")
#define MBARRIER_WAIT_PARITY(mb, par) do { \
    uint32_t _mb = (uint32_t)(mb), _p = (uint32_t)(par), _done; \
    asm volatile("{\n\t.reg .pred p;\n\t" \
        "mbarrier.try_wait.parity.acquire.cta.shared::cta.b64 p, [%1], %2;\n\t" \
        "selp.b32 %0, 1, 0, p;\n\t}" : "=r"(_done) : "r"(_mb), "r"(_p) : "memory"); \
    if (!_done) { \
        asm volatile("{\n\t.reg .pred P1;\n\t" \
            "WL_%=:\n\t" \
            "mbarrier.try_wait.parity.acquire.cta.shared::cta.b64 P1, [%0], %1, 0x989680;\n\t" \
            "@P1 bra.uni WD_%=;\n\t" \
            "bra.uni WL_%=;\n\t" \
            "WD_%=:\n\t}" :: "r"(_mb), "r"(_p) : "memory"); \
    } \
} while (0)

// ---------------- K0: zero accumulators (every launch) ----------------
__global__ void k_zero() {
    int i = blockIdx.x * blockDim.x + threadIdx.x;
    if (i < NN) { g_colsum[i] = 0.f; g_sumsq[i] = 0.f; g_rowsum[i] = 0.f; }
}

// ---------------- K2: transpose + bf16 convert + fused column stats ----------------
__global__ void k_transpose(const float* __restrict__ qi, const float* __restrict__ qj) {
    __shared__ float s_s[8][33];
    __shared__ float s_s2[8][33];
    int b0 = blockIdx.x * 64;
    int r0 = blockIdx.y * 32;
    const float* q = (r0 < CLS) ? qi : qj;
    int c0 = (r0 < CLS) ? r0 : (r0 - CLS);
    int tx = threadIdx.x, ty = threadIdx.y;

    const float* src = q + (size_t)(b0 + ty * 8) * CLS + c0 + tx;
    float s = 0.f, s2 = 0.f;
    uint32_t packed[4];
#pragma unroll
    for (int g = 0; g < 4; ++g) {
        float v0 = src[(size_t)(g * 2 + 0) * CLS];
        float v1 = src[(size_t)(g * 2 + 1) * CLS];
        s += v0 + v1;
        s2 += v0 * v0 + v1 * v1;
        __nv_bfloat162 h = __floats2bfloat162_rn(v0, v1);
        packed[g] = *(uint32_t*)&h;
    }
    *(uint4*)(g_X + (size_t)(r0 + tx) * BATCH + b0 + ty * 8) =
        make_uint4(packed[0], packed[1], packed[2], packed[3]);

    s_s[ty][tx] = s;
    s_s2[ty][tx] = s2;
    __syncthreads();
    if (ty == 0) {
        float ts = 0.f, ts2 = 0.f;
#pragma unroll
        for (int w = 0; w < 8; ++w) { ts += s_s[w][tx]; ts2 += s_s2[w][tx]; }
        atomicAdd(&g_colsum[r0 + tx], ts);
        atomicAdd(&g_sumsq[r0 + tx], ts2);
    }
}

// ---------------- K3: bf16 GEMM (256 thr, 32x64 warp tiles, mbarrier ring,
//                    ks-level fragment double-buffering) ----------------
__global__ void __launch_bounds__(256, 2) k_gemm() {
    extern __shared__ __align__(128) uint8_t smem[];
    const uint32_t smem_base = smem_u32(smem);
    const int tid = threadIdx.x;
    const int lane = tid & 31;
    const int warp = tid >> 5;
    const int wm = warp >> 1;   // 0..3 (32 rows each)
    const int wn = warp & 1;    // 0..1 (64 cols each)

    // triangular tile decode: blockIdx.x -> (bi <= bj)
    int t = blockIdx.x;
    int u = (NTRI - 1) - t;
    int k = (int)((sqrtf((float)(8 * u + 1)) - 1.0f) * 0.5f);
    while (k * (k + 1) / 2 > u) --k;
    while ((k + 1) * (k + 2) / 2 <= u) ++k;
    const int bi = (NT1D - 1) - k;
    const int bj = (NT1D - 1) - (u - k * (k + 1) / 2);
    const int M0 = bi * TM;
    const int C0 = bj * TN;
    const bool diag = (bi == bj);
    const bool ptile = (bj == bi + (CLS / TM));   // partner-diagonal block

    // mbarriers: full[0..2] at SMEM_BYTES+0/8/16, empty[0..2] at +24/32/40
#define MB_FULL(s)  (smem_base + (uint32_t)SMEM_BYTES + (uint32_t)((s) * 8))
#define MB_EMPTY(s) (smem_base + (uint32_t)SMEM_BYTES + 24u + (uint32_t)((s) * 8))
    if (tid < 3) {
        MBARRIER_INIT(MB_FULL(tid), 256);
        MBARRIER_INIT(MB_EMPTY(tid), 256);
    }
    __syncthreads();

    // ---- per-thread cp.async plumbing: 8 chunks of 16B per stage-issue ----
    const int rowt = tid >> 3;        // 0..31
    const int jt = tid & 7;           // 16B column within 128B row
    const __nv_bfloat16* srcA = g_X + (size_t)(M0 + rowt) * BATCH + jt * 8;
    const __nv_bfloat16* srcB = g_X + (size_t)(C0 + rowt) * BATCH + jt * 8;
    const uint32_t dstA = (uint32_t)(rowt * PITCHB + jt * 16);
    const uint32_t dstB = dstA + (uint32_t)A_STAGE;

    float acc[2][8][4];
#pragma unroll
    for (int mt = 0; mt < 2; ++mt)
#pragma unroll
        for (int nt = 0; nt < 8; ++nt)
#pragma unroll
            for (int v = 0; v < 4; ++v) acc[mt][nt][v] = 0.f;

    // per-lane ldsm base offsets (byte units, slot 0)
    const uint32_t a_off = smem_base +
        (uint32_t)((wm * 32 + (lane & 15)) * PITCHB + (lane >> 4) * 16);
    const uint32_t b_off = smem_base + (uint32_t)A_STAGE +
        (uint32_t)((wn * 64 + ((lane >> 4) & 1) * 8 + (lane & 7)) * PITCHB +
                   ((lane >> 3) & 1) * 16);

#define ISSUE_STAGE(SLOT)                                                         \
    do {                                                                          \
        uint32_t db = smem_base + (uint32_t)((SLOT) * STAGE_BYTES);               \
        _Pragma("unroll")                                                         \
        for (int i = 0; i < 4; ++i) {                                             \
            cp_async16s(db + dstA + (uint32_t)(i * 32 * PITCHB),                  \
                        srcA + (size_t)i * 32 * BATCH);                           \
            cp_async16s(db + dstB + (uint32_t)(i * 32 * PITCHB),                  \
                        srcB + (size_t)i * 32 * BATCH);                           \
        }                                                                         \
        srcA += BKE;                                                              \
        srcB += BKE;                                                              \
        CPASYNC_MBAR_ARRIVE(MB_FULL(SLOT));                                       \
    } while (0)

#define LOAD_FRAGS(BUF, aB, bB, KS)                                               \
    do {                                                                          \
        _Pragma("unroll")                                                         \
        for (int mt = 0; mt < 2; ++mt)                                            \
            ldsm4(fa[BUF][mt][0], fa[BUF][mt][1], fa[BUF][mt][2], fa[BUF][mt][3], \
                  (aB) + (uint32_t)(mt * 16 * PITCHB + (KS) * 32));               \
        _Pragma("unroll")                                                         \
        for (int i = 0; i < 4; ++i)                                               \
            ldsm4(fb[BUF][i][0], fb[BUF][i][1], fb[BUF][i][2], fb[BUF][i][3],     \
                  (bB) + (uint32_t)(i * 16 * PITCHB + (KS) * 32));                \
    } while (0)

#define MMA_FRAGS(BUF)                                                            \
    do {                                                                          \
        _Pragma("unroll")                                                         \
        for (int mt = 0; mt < 2; ++mt)                                            \
            _Pragma("unroll")                                                     \
            for (int nt = 0; nt < 8; ++nt)                                        \
                mma_bf16(acc[mt][nt], fa[BUF][mt],                                \
                         fb[BUF][nt >> 1][(nt & 1) * 2],                          \
                         fb[BUF][nt >> 1][(nt & 1) * 2 + 1]);                     \
    } while (0)

#define COMPUTE_STAGE(S)                                                          \
    do {                                                                          \
        const uint32_t aB = a_off + (uint32_t)((S) * STAGE_BYTES);                \
        const uint32_t bB = b_off + (uint32_t)((S) * STAGE_BYTES);                \
        uint32_t fa[2][2][4];                                                     \
        uint32_t fb[2][4][4];                                                     \
        LOAD_FRAGS(0, aB, bB, 0);                                                 \
        LOAD_FRAGS(1, aB, bB, 1);                                                 \
        MMA_FRAGS(0);                                                             \
        LOAD_FRAGS(0, aB, bB, 2);                                                 \
        MMA_FRAGS(1);                                                             \
        LOAD_FRAGS(1, aB, bB, 3);                                                 \
        MMA_FRAGS(0);                                                             \
        MMA_FRAGS(1);                                                             \
    } while (0)

    // ---- prologue: stages 0,1 into slots 0,1 ----
    ISSUE_STAGE(0);
    ISSUE_STAGE(1);

    // ---- main: 84 blocks x 3 stages; parities are functions of ib ----
    for (int ib = 0; ib < 84; ++ib) {
        const uint32_t pf = (uint32_t)(ib & 1);
        // s = 0: fill slot2 (freed at prev block s=2), consume slot0
        if (ib) MBARRIER_WAIT_PARITY(MB_EMPTY(2), pf ^ 1u);
        ISSUE_STAGE(2);
        MBARRIER_WAIT_PARITY(MB_FULL(0), pf);
        COMPUTE_STAGE(0);
        MBARRIER_ARRIVE(MB_EMPTY(0));
        // s = 1: fill slot0 (freed just above), consume slot1
        MBARRIER_WAIT_PARITY(MB_EMPTY(0), pf);
        ISSUE_STAGE(0);
        MBARRIER_WAIT_PARITY(MB_FULL(1), pf);
        COMPUTE_STAGE(1);
        MBARRIER_ARRIVE(MB_EMPTY(1));
        // s = 2: fill slot1, consume slot2
        MBARRIER_WAIT_PARITY(MB_EMPTY(1), pf);
        ISSUE_STAGE(1);
        MBARRIER_WAIT_PARITY(MB_FULL(2), pf);
        COMPUTE_STAGE(2);
        MBARRIER_ARRIVE(MB_EMPTY(2));
    }
    // ---- tail: stages 252..255 in slots 0,1,2,0 ----
    MBARRIER_WAIT_PARITY(MB_EMPTY(2), 1u);
    ISSUE_STAGE(2);                           // stage 254
    MBARRIER_WAIT_PARITY(MB_FULL(0), 0u);
    COMPUTE_STAGE(0);                         // stage 252
    MBARRIER_ARRIVE(MB_EMPTY(0));
    MBARRIER_WAIT_PARITY(MB_EMPTY(0), 0u);
    ISSUE_STAGE(0);                           // stage 255
    MBARRIER_WAIT_PARITY(MB_FULL(1), 0u);
    COMPUTE_STAGE(1);                         // stage 253
    MBARRIER_WAIT_PARITY(MB_FULL(2), 0u);
    COMPUTE_STAGE(2);                         // stage 254
    MBARRIER_WAIT_PARITY(MB_FULL(0), 1u);
    COMPUTE_STAGE(0);                         // stage 255

#undef COMPUTE_STAGE
#undef MMA_FRAGS
#undef LOAD_FRAGS
#undef ISSUE_STAGE

    // ---------- fused epilogue ----------
    __syncthreads();
    float* s_inv = (float*)smem;      // [0..127]=row invn, [128..255]=col invn
    s_inv[tid] = rsqrtf(fmaxf((tid < 128) ? g_sumsq[M0 + tid]
                                          : g_sumsq[C0 + tid - 128], 1e-30f));
    __syncthreads();

    const int r_loc0 = wm * 32 + (lane >> 2);
    const int c_loc0 = wn * 64 + (lane & 3) * 2;
    float csum[8][2];
#pragma unroll
    for (int nt = 0; nt < 8; ++nt) { csum[nt][0] = 0.f; csum[nt][1] = 0.f; }

#pragma unroll
    for (int mt = 0; mt < 2; ++mt) {
        const int rA = r_loc0 + mt * 16;
        const int rB = rA + 8;
        const float invA = s_inv[rA], invB = s_inv[rB];
        float sA = 0.f, sB = 0.f;
#pragma unroll
        for (int nt = 0; nt < 8; ++nt) {
            const int c0l = c_loc0 + nt * 8;
            const float ic0 = s_inv[128 + c0l], ic1 = s_inv[128 + c0l + 1];
            const float simA0 = acc[mt][nt][0] * invA * ic0;
            const float simA1 = acc[mt][nt][1] * invA * ic1;
            const float simB0 = acc[mt][nt][2] * invB * ic0;
            const float simB1 = acc[mt][nt][3] * invB * ic1;
            if (ptile) {   // partner: global col == global row + CLS  <=> same local idx
                if (rA == c0l)     { g_pos[M0 + rA] = simA0; g_pos[C0 + c0l] = simA0; }
                if (rA == c0l + 1) { g_pos[M0 + rA] = simA1; g_pos[C0 + c0l + 1] = simA1; }
                if (rB == c0l)     { g_pos[M0 + rB] = simB0; g_pos[C0 + c0l] = simB0; }
                if (rB == c0l + 1) { g_pos[M0 + rB] = simB1; g_pos[C0 + c0l + 1] = simB1; }
            }
            float eA0 = __expf(simA0), eA1 = __expf(simA1);
            float eB0 = __expf(simB0), eB1 = __expf(simB1);
            if (diag) {   // exclude self
                if (rA == c0l)     eA0 = 0.f;
                if (rA == c0l + 1) eA1 = 0.f;
                if (rB == c0l)     eB0 = 0.f;
                if (rB == c0l + 1) eB1 = 0.f;
            }
            sA += eA0 + eA1;
            sB += eB0 + eB1;
            if (!diag) {   // symmetric: same values feed the transposed rows
                csum[nt][0] += eA0 + eB0;
                csum[nt][1] += eA1 + eB1;
            }
        }
        sA += __shfl_xor_sync(0xffffffffu, sA, 1);
        sA += __shfl_xor_sync(0xffffffffu, sA, 2);
        sB += __shfl_xor_sync(0xffffffffu, sB, 1);
        sB += __shfl_xor_sync(0xffffffffu, sB, 2);
        if ((lane & 3) == 0) {
            atomicAdd(&g_rowsum[M0 + rA], sA);
            atomicAdd(&g_rowsum[M0 + rB], sB);
        }
    }
    if (!diag) {
#pragma unroll
        for (int nt = 0; nt < 8; ++nt)
#pragma unroll
            for (int v = 0; v < 2; ++v) {
                float x = csum[nt][v];
                x += __shfl_xor_sync(0xffffffffu, x, 4);
                x += __shfl_xor_sync(0xffffffffu, x, 8);
                x += __shfl_xor_sync(0xffffffffu, x, 16);
                if (lane < 4)
                    atomicAdd(&g_rowsum[C0 + wn * 64 + nt * 8 + lane * 2 + v], x);
            }
    }
}

// ---------------- K5: entropy + ce combine ----------------
__global__ void k_final(float* out) {
    __shared__ double sC[256], sTi[256], sSi[256], sTj[256], sSj[256];
    int t = threadIdx.x;
    double ce = 0.0;
    for (int r = t; r < NN; r += 256)
        ce += (double)logf(g_rowsum[r]) - (double)g_pos[r];
    double Ti = 0, Si = 0, Tj = 0, Sj = 0;
    for (int c = t; c < CLS; c += 256) {
        double v = (double)g_colsum[c];
        Ti += v; Si += v * log(v);
        double w = (double)g_colsum[c + CLS];
        Tj += w; Sj += w * log(w);
    }
    sC[t] = ce; sTi[t] = Ti; sSi[t] = Si; sTj[t] = Tj; sSj[t] = Sj;
    __syncthreads();
#pragma unroll
    for (int off = 128; off > 0; off >>= 1) {
        if (t < off) {
            sC[t] += sC[t + off];
            sTi[t] += sTi[t + off]; sSi[t] += sSi[t + off];
            sTj[t] += sTj[t + off]; sSj[t] += sSj[t + off];
        }
        __syncthreads();
    }
    if (t == 0) {
        double nei = log((double)CLS) - log(sTi[0]) + sSi[0] / sTi[0];
        double nej = log((double)CLS) - log(sTj[0]) + sSj[0] / sTj[0];
        out[0] = (float)(sC[0] / (double)NN + nei + nej);
    }
}

// ---------------- launch ----------------
extern "C" void kernel_launch(void* const* d_in, const int* in_sizes, int n_in,
                              void* d_out, int out_size) {
    const float* qi = (const float*)d_in[0];
    const float* qj = (const float*)d_in[1];
    float* out = (float*)d_out;

    cudaFuncSetAttribute(k_gemm, cudaFuncAttributeMaxDynamicSharedMemorySize, SMEM_TOTAL);

    k_zero<<<NN / 256, 256>>>();
    k_transpose<<<dim3(BATCH / 64, NN / 32), dim3(32, 8)>>>(qi, qj);
    k_gemm<<<NTRI, 256, SMEM_TOTAL>>>();
    k_final<<<1, 256>>>(out);
}

// round 17
// speedup vs baseline: 1.0544x; 1.0544x over previous
#include <cuda_runtime.h>
#include <cuda_bf16.h>
#include <cstdint>
#include <cstddef>

#define BATCH 16384
#define CLS   2048
#define NN    4096   // 2*CLS

// ---------------- BF16 GEMM config ----------------
#define TM 128
#define TN 128
#define BKE 64                 // bf16 elems per stage row = 128 bytes
#define PITCHB 144             // bytes per smem row (128 data + 16 pad, conflict-free ldmatrix)
#define STAGES 3
#define NITER (BATCH / BKE)    // 256
#define A_STAGE (TM * PITCHB)  // 18432 bytes
#define STAGE_BYTES (2 * A_STAGE)            // 36864
#define SMEM_BYTES (STAGES * STAGE_BYTES)    // 110592
#define SMEM_TOTAL (SMEM_BYTES + 64)         // + mbarriers
#define NT1D (NN / TM)                        // 32
#define NTRI (NT1D * (NT1D + 1) / 2)          // 528 upper-triangular tiles

// ---------------- scratch (device globals) ----------------
__device__ __align__(16) __nv_bfloat16 g_X[(size_t)NN * BATCH];  // 128MB, K-major bf16
__device__ float g_colsum[NN];
__device__ float g_sumsq[NN];
__device__ float g_rowsum[NN];   // sum_{s!=r} exp(sim[r,s])
__device__ float g_pos[NN];      // sim[r, r^CLS]
__device__ double g_acc[5];      // 0=ce, 1=Ti, 2=Si, 3=Tj, 4=Sj

// ---------------- helpers ----------------
__device__ __forceinline__ uint32_t smem_u32(const void* p) {
    uint32_t a;
    asm("{ .reg .u64 t; cvta.to.shared.u64 t, %1; cvt.u32.u64 %0, t; }" : "=r"(a) : "l"(p));
    return a;
}
__device__ __forceinline__ void cp_async16s(uint32_t dst, const void* src) {
    asm volatile("cp.async.cg.shared.global [%0], [%1], 16;\n" :: "r"(dst), "l"(src));
}
__device__ __forceinline__ void ldsm4(uint32_t& r0, uint32_t& r1, uint32_t& r2, uint32_t& r3,
                                      uint32_t addr) {
    asm volatile("ldmatrix.sync.aligned.m8n8.x4.shared.b16 {%0,%1,%2,%3}, [%4];\n"
                 : "=r"(r0), "=r"(r1), "=r"(r2), "=r"(r3) : "r"(addr));
}
// bf16 mma: m16n8k16, fp32 accum
__device__ __forceinline__ void mma_bf16(float* c, const uint32_t* a, uint32_t b0, uint32_t b1) {
    asm volatile(
        "mma.sync.aligned.m16n8k16.row.col.f32.bf16.bf16.f32 "
        "{%0,%1,%2,%3}, {%4,%5,%6,%7}, {%8,%9}, {%0,%1,%2,%3};\n"
        : "+f"(c[0]), "+f"(c[1]), "+f"(c[2]), "+f"(c[3])
        : "r"(a[0]), "r"(a[1]), "r"(a[2]), "r"(a[3]), "r"(b0), "r"(b1));
}

// ---------------- mbarrier primitives (base ISA) ----------------
#define MBARRIER_INIT(mb, cnt) \
    asm volatile("mbarrier.init.shared.b64 [%0], %1;" :: "r"((uint32_t)(mb)), "r"((uint32_t)(cnt)) : "memory")
#define MBARRIER_ARRIVE(mb) \
    asm volatile("mbarrier.arrive.shared.b64 _, [%0];" :: "r"((uint32_t)(mb)) : "memory")
#define CPASYNC_MBAR_ARRIVE(mb) \
    asm volatile("cp.async.mbarrier.arrive.noinc.shared.b64 [%0];" :: "r"((uint32_t)(mb)) : "memory")
#define MBARRIER_WAIT_PARITY(mb, par) do { \
    uint32_t _mb = (uint32_t)(mb), _p = (uint32_t)(par), _done; \
    asm volatile("{\n\t.reg .pred p;\n\t" \
        "mbarrier.try_wait.parity.acquire.cta.shared::cta.b64 p, [%1], %2;\n\t" \
        "selp.b32 %0, 1, 0, p;\n\t}" : "=r"(_done) : "r"(_mb), "r"(_p) : "memory"); \
    if (!_done) { \
        asm volatile("{\n\t.reg .pred P1;\n\t" \
            "WL_%=:\n\t" \
            "mbarrier.try_wait.parity.acquire.cta.shared::cta.b64 P1, [%0], %1, 0x989680;\n\t" \
            "@P1 bra.uni WD_%=;\n\t" \
            "bra.uni WL_%=;\n\t" \
            "WD_%=:\n\t}" :: "r"(_mb), "r"(_p) : "memory"); \
    } \
} while (0)

// ---------------- K0: zero accumulators (every launch) ----------------
__global__ void k_zero() {
    int i = blockIdx.x * blockDim.x + threadIdx.x;
    if (i < NN) { g_colsum[i] = 0.f; g_sumsq[i] = 0.f; g_rowsum[i] = 0.f; }
    if (i < 5) g_acc[i] = 0.0;
}

// ---------------- K2: transpose + bf16 convert + fused column stats ----------------
__global__ void k_transpose(const float* __restrict__ qi, const float* __restrict__ qj) {
    __shared__ float s_s[8][33];
    __shared__ float s_s2[8][33];
    int b0 = blockIdx.x * 64;
    int r0 = blockIdx.y * 32;
    const float* q = (r0 < CLS) ? qi : qj;
    int c0 = (r0 < CLS) ? r0 : (r0 - CLS);
    int tx = threadIdx.x, ty = threadIdx.y;

    const float* src = q + (size_t)(b0 + ty * 8) * CLS + c0 + tx;
    float s = 0.f, s2 = 0.f;
    uint32_t packed[4];
#pragma unroll
    for (int g = 0; g < 4; ++g) {
        float v0 = src[(size_t)(g * 2 + 0) * CLS];
        float v1 = src[(size_t)(g * 2 + 1) * CLS];
        s += v0 + v1;
        s2 += v0 * v0 + v1 * v1;
        __nv_bfloat162 h = __floats2bfloat162_rn(v0, v1);
        packed[g] = *(uint32_t*)&h;
    }
    *(uint4*)(g_X + (size_t)(r0 + tx) * BATCH + b0 + ty * 8) =
        make_uint4(packed[0], packed[1], packed[2], packed[3]);

    s_s[ty][tx] = s;
    s_s2[ty][tx] = s2;
    __syncthreads();
    if (ty == 0) {
        float ts = 0.f, ts2 = 0.f;
#pragma unroll
        for (int w = 0; w < 8; ++w) { ts += s_s[w][tx]; ts2 += s_s2[w][tx]; }
        atomicAdd(&g_colsum[r0 + tx], ts);
        atomicAdd(&g_sumsq[r0 + tx], ts2);
    }
}

// ---------------- K3: bf16 GEMM (256 thr, 32x64 warp tiles, mbarrier ring) ----------------
__global__ void __launch_bounds__(256, 2) k_gemm() {
    extern __shared__ __align__(128) uint8_t smem[];
    const uint32_t smem_base = smem_u32(smem);
    const int tid = threadIdx.x;
    const int lane = tid & 31;
    const int warp = tid >> 5;
    const int wm = warp >> 1;   // 0..3 (32 rows each)
    const int wn = warp & 1;    // 0..1 (64 cols each)

    // triangular tile decode: blockIdx.x -> (bi <= bj)
    int t = blockIdx.x;
    int u = (NTRI - 1) - t;
    int k = (int)((sqrtf((float)(8 * u + 1)) - 1.0f) * 0.5f);
    while (k * (k + 1) / 2 > u) --k;
    while ((k + 1) * (k + 2) / 2 <= u) ++k;
    const int bi = (NT1D - 1) - k;
    const int bj = (NT1D - 1) - (u - k * (k + 1) / 2);
    const int M0 = bi * TM;
    const int C0 = bj * TN;
    const bool diag = (bi == bj);
    const bool ptile = (bj == bi + (CLS / TM));   // partner-diagonal block

    // mbarriers: full[0..2] at SMEM_BYTES+0/8/16, empty[0..2] at +24/32/40
#define MB_FULL(s)  (smem_base + (uint32_t)SMEM_BYTES + (uint32_t)((s) * 8))
#define MB_EMPTY(s) (smem_base + (uint32_t)SMEM_BYTES + 24u + (uint32_t)((s) * 8))
    if (tid < 3) {
        MBARRIER_INIT(MB_FULL(tid), 256);
        MBARRIER_INIT(MB_EMPTY(tid), 256);
    }
    __syncthreads();

    // ---- per-thread cp.async plumbing: 8 chunks of 16B per stage-issue ----
    const int rowt = tid >> 3;        // 0..31
    const int jt = tid & 7;           // 16B column within 128B row
    const __nv_bfloat16* srcA = g_X + (size_t)(M0 + rowt) * BATCH + jt * 8;
    const __nv_bfloat16* srcB = g_X + (size_t)(C0 + rowt) * BATCH + jt * 8;
    const uint32_t dstA = (uint32_t)(rowt * PITCHB + jt * 16);
    const uint32_t dstB = dstA + (uint32_t)A_STAGE;

    float acc[2][8][4];
#pragma unroll
    for (int mt = 0; mt < 2; ++mt)
#pragma unroll
        for (int nt = 0; nt < 8; ++nt)
#pragma unroll
            for (int v = 0; v < 4; ++v) acc[mt][nt][v] = 0.f;

    // per-lane ldsm base offsets (byte units, slot 0)
    const uint32_t a_off = smem_base +
        (uint32_t)((wm * 32 + (lane & 15)) * PITCHB + (lane >> 4) * 16);
    const uint32_t b_off = smem_base + (uint32_t)A_STAGE +
        (uint32_t)((wn * 64 + ((lane >> 4) & 1) * 8 + (lane & 7)) * PITCHB +
                   ((lane >> 3) & 1) * 16);

#define ISSUE_STAGE(SLOT)                                                         \
    do {                                                                          \
        uint32_t db = smem_base + (uint32_t)((SLOT) * STAGE_BYTES);               \
        _Pragma("unroll")                                                         \
        for (int i = 0; i < 4; ++i) {                                             \
            cp_async16s(db + dstA + (uint32_t)(i * 32 * PITCHB),                  \
                        srcA + (size_t)i * 32 * BATCH);                           \
            cp_async16s(db + dstB + (uint32_t)(i * 32 * PITCHB),                  \
                        srcB + (size_t)i * 32 * BATCH);                           \
        }                                                                         \
        srcA += BKE;                                                              \
        srcB += BKE;                                                              \
        CPASYNC_MBAR_ARRIVE(MB_FULL(SLOT));                                       \
    } while (0)

#define COMPUTE_STAGE(S)                                                          \
    do {                                                                          \
        const uint32_t aB = a_off + (uint32_t)((S) * STAGE_BYTES);                \
        const uint32_t bB = b_off + (uint32_t)((S) * STAGE_BYTES);                \
        _Pragma("unroll")                                                         \
        for (int ks = 0; ks < 4; ++ks) {                                          \
            uint32_t a[2][4];                                                     \
            _Pragma("unroll")                                                     \
            for (int mt = 0; mt < 2; ++mt)                                        \
                ldsm4(a[mt][0], a[mt][1], a[mt][2], a[mt][3],                     \
                      aB + (uint32_t)(mt * 16 * PITCHB + ks * 32));               \
            uint32_t b[4][4];                                                     \
            _Pragma("unroll")                                                     \
            for (int i = 0; i < 4; ++i)                                           \
                ldsm4(b[i][0], b[i][1], b[i][2], b[i][3],                         \
                      bB + (uint32_t)(i * 16 * PITCHB + ks * 32));                \
            _Pragma("unroll")                                                     \
            for (int mt = 0; mt < 2; ++mt)                                        \
                _Pragma("unroll")                                                 \
                for (int nt = 0; nt < 8; ++nt)                                    \
                    mma_bf16(acc[mt][nt], a[mt],                                  \
                             b[nt >> 1][(nt & 1) * 2], b[nt >> 1][(nt & 1) * 2 + 1]); \
        }                                                                         \
    } while (0)

    // ---- prologue: stages 0,1 into slots 0,1 ----
    ISSUE_STAGE(0);
    ISSUE_STAGE(1);

    // ---- main: 84 blocks x 3 stages; parities are functions of ib ----
    for (int ib = 0; ib < 84; ++ib) {
        const uint32_t pf = (uint32_t)(ib & 1);
        // s = 0: fill slot2 (freed at prev block s=2), consume slot0
        if (ib) MBARRIER_WAIT_PARITY(MB_EMPTY(2), pf ^ 1u);
        ISSUE_STAGE(2);
        MBARRIER_WAIT_PARITY(MB_FULL(0), pf);
        COMPUTE_STAGE(0);
        MBARRIER_ARRIVE(MB_EMPTY(0));
        // s = 1: fill slot0 (freed just above), consume slot1
        MBARRIER_WAIT_PARITY(MB_EMPTY(0), pf);
        ISSUE_STAGE(0);
        MBARRIER_WAIT_PARITY(MB_FULL(1), pf);
        COMPUTE_STAGE(1);
        MBARRIER_ARRIVE(MB_EMPTY(1));
        // s = 2: fill slot1, consume slot2
        MBARRIER_WAIT_PARITY(MB_EMPTY(1), pf);
        ISSUE_STAGE(1);
        MBARRIER_WAIT_PARITY(MB_FULL(2), pf);
        COMPUTE_STAGE(2);
        MBARRIER_ARRIVE(MB_EMPTY(2));
    }
    // ---- tail: stages 252..255 in slots 0,1,2,0 ----
    MBARRIER_WAIT_PARITY(MB_EMPTY(2), 1u);
    ISSUE_STAGE(2);                           // stage 254
    MBARRIER_WAIT_PARITY(MB_FULL(0), 0u);
    COMPUTE_STAGE(0);                         // stage 252
    MBARRIER_ARRIVE(MB_EMPTY(0));
    MBARRIER_WAIT_PARITY(MB_EMPTY(0), 0u);
    ISSUE_STAGE(0);                           // stage 255
    MBARRIER_WAIT_PARITY(MB_FULL(1), 0u);
    COMPUTE_STAGE(1);                         // stage 253
    MBARRIER_WAIT_PARITY(MB_FULL(2), 0u);
    COMPUTE_STAGE(2);                         // stage 254
    MBARRIER_WAIT_PARITY(MB_FULL(0), 1u);
    COMPUTE_STAGE(0);                         // stage 255

#undef COMPUTE_STAGE
#undef ISSUE_STAGE

    // ---------- fused epilogue ----------
    __syncthreads();
    float* s_inv = (float*)smem;      // [0..127]=row invn, [128..255]=col invn
    s_inv[tid] = rsqrtf(fmaxf((tid < 128) ? g_sumsq[M0 + tid]
                                          : g_sumsq[C0 + tid - 128], 1e-30f));
    __syncthreads();

    const int r_loc0 = wm * 32 + (lane >> 2);
    const int c_loc0 = wn * 64 + (lane & 3) * 2;
    float csum[8][2];
#pragma unroll
    for (int nt = 0; nt < 8; ++nt) { csum[nt][0] = 0.f; csum[nt][1] = 0.f; }

#pragma unroll
    for (int mt = 0; mt < 2; ++mt) {
        const int rA = r_loc0 + mt * 16;
        const int rB = rA + 8;
        const float invA = s_inv[rA], invB = s_inv[rB];
        float sA = 0.f, sB = 0.f;
#pragma unroll
        for (int nt = 0; nt < 8; ++nt) {
            const int c0l = c_loc0 + nt * 8;
            const float ic0 = s_inv[128 + c0l], ic1 = s_inv[128 + c0l + 1];
            const float simA0 = acc[mt][nt][0] * invA * ic0;
            const float simA1 = acc[mt][nt][1] * invA * ic1;
            const float simB0 = acc[mt][nt][2] * invB * ic0;
            const float simB1 = acc[mt][nt][3] * invB * ic1;
            if (ptile) {   // partner: global col == global row + CLS  <=> same local idx
                if (rA == c0l)     { g_pos[M0 + rA] = simA0; g_pos[C0 + c0l] = simA0; }
                if (rA == c0l + 1) { g_pos[M0 + rA] = simA1; g_pos[C0 + c0l + 1] = simA1; }
                if (rB == c0l)     { g_pos[M0 + rB] = simB0; g_pos[C0 + c0l] = simB0; }
                if (rB == c0l + 1) { g_pos[M0 + rB] = simB1; g_pos[C0 + c0l + 1] = simB1; }
            }
            float eA0 = __expf(simA0), eA1 = __expf(simA1);
            float eB0 = __expf(simB0), eB1 = __expf(simB1);
            if (diag) {   // exclude self
                if (rA == c0l)     eA0 = 0.f;
                if (rA == c0l + 1) eA1 = 0.f;
                if (rB == c0l)     eB0 = 0.f;
                if (rB == c0l + 1) eB1 = 0.f;
            }
            sA += eA0 + eA1;
            sB += eB0 + eB1;
            if (!diag) {   // symmetric: same values feed the transposed rows
                csum[nt][0] += eA0 + eB0;
                csum[nt][1] += eA1 + eB1;
            }
        }
        sA += __shfl_xor_sync(0xffffffffu, sA, 1);
        sA += __shfl_xor_sync(0xffffffffu, sA, 2);
        sB += __shfl_xor_sync(0xffffffffu, sB, 1);
        sB += __shfl_xor_sync(0xffffffffu, sB, 2);
        if ((lane & 3) == 0) {
            atomicAdd(&g_rowsum[M0 + rA], sA);
            atomicAdd(&g_rowsum[M0 + rB], sB);
        }
    }
    if (!diag) {
#pragma unroll
        for (int nt = 0; nt < 8; ++nt)
#pragma unroll
            for (int v = 0; v < 2; ++v) {
                float x = csum[nt][v];
                x += __shfl_xor_sync(0xffffffffu, x, 4);
                x += __shfl_xor_sync(0xffffffffu, x, 8);
                x += __shfl_xor_sync(0xffffffffu, x, 16);
                if (lane < 4)
                    atomicAdd(&g_rowsum[C0 + wn * 64 + nt * 8 + lane * 2 + v], x);
            }
    }
}

// ---------------- K4: parallel reduction of ce + entropy terms ----------------
__global__ void k_red() {
    __shared__ double sh[5][256];
    int t = threadIdx.x;
    int idx = blockIdx.x * 256 + t;   // 0..4095

    double ce = (double)logf(g_rowsum[idx]) - (double)g_pos[idx];
    double Ti = 0, Si = 0, Tj = 0, Sj = 0;
    if (idx < CLS) {
        double v = (double)g_colsum[idx];
        Ti = v; Si = v * log(v);
        double w = (double)g_colsum[idx + CLS];
        Tj = w; Sj = w * log(w);
    }
    sh[0][t] = ce; sh[1][t] = Ti; sh[2][t] = Si; sh[3][t] = Tj; sh[4][t] = Sj;
    __syncthreads();
#pragma unroll
    for (int off = 128; off > 0; off >>= 1) {
        if (t < off) {
#pragma unroll
            for (int a = 0; a < 5; ++a) sh[a][t] += sh[a][t + off];
        }
        __syncthreads();
    }
    if (t == 0) {
#pragma unroll
        for (int a = 0; a < 5; ++a) atomicAdd(&g_acc[a], sh[a][0]);
    }
}

// ---------------- K5: final combine (1 thread) ----------------
__global__ void k_out(float* out) {
    double ce = g_acc[0], Ti = g_acc[1], Si = g_acc[2], Tj = g_acc[3], Sj = g_acc[4];
    double nei = log((double)CLS) - log(Ti) + Si / Ti;
    double nej = log((double)CLS) - log(Tj) + Sj / Tj;
    out[0] = (float)(ce / (double)NN + nei + nej);
}

// ---------------- launch ----------------
extern "C" void kernel_launch(void* const* d_in, const int* in_sizes, int n_in,
                              void* d_out, int out_size) {
    const float* qi = (const float*)d_in[0];
    const float* qj = (const float*)d_in[1];
    float* out = (float*)d_out;

    cudaFuncSetAttribute(k_gemm, cudaFuncAttributeMaxDynamicSharedMemorySize, SMEM_TOTAL);

    k_zero<<<NN / 256, 256>>>();
    k_transpose<<<dim3(BATCH / 64, NN / 32), dim3(32, 8)>>>(qi, qj);
    k_gemm<<<NTRI, 256, SMEM_TOTAL>>>();
    k_red<<<NN / 256, 256>>>();
    k_out<<<1, 1>>>(out);
}